// round 8
// baseline (speedup 1.0000x reference)
#include <cuda_runtime.h>
#include <cuda_bf16.h>
#include <math.h>
#include <stdint.h>

#define B_ 32
#define D_ 512
#define N_ 2048
#define K_ 64

// ---------------------------------------------------------------------------
// Scratch (static device globals; no allocations allowed)
__device__ __align__(16) __nv_bfloat16 g_Wh[K_ * D_];                 // W hi plane
__device__ __align__(16) __nv_bfloat16 g_Wl[K_ * D_];                 // W lo plane
__device__ __align__(16) __nv_bfloat16 g_Xh[(size_t)B_ * D_ * N_];    // x hi plane (67MB)
__device__ __align__(16) __nv_bfloat16 g_Xl[(size_t)B_ * D_ * N_];    // x lo plane (67MB)
__device__ __align__(16) __nv_bfloat16 g_Sh[(size_t)B_ * K_ * N_];    // scores hi
__device__ __align__(16) __nv_bfloat16 g_Sl[(size_t)B_ * K_ * N_];    // scores lo
__device__ __align__(16) float g_ssum[B_ * K_];
__device__ __align__(16) float g_aggp[4][(size_t)B_ * D_ * K_];       // split-K parts
__device__ __align__(16) float g_colss[B_ * K_];
__device__ __align__(16) float g_mult[B_ * K_];

// ---------------------------------------------------------------------------
__device__ __forceinline__ uint32_t smem_u32(const void* p) {
    uint32_t a;
    asm("{ .reg .u64 t; cvta.to.shared.u64 t, %1; cvt.u32.u64 %0, t; }" : "=r"(a) : "l"(p));
    return a;
}
__device__ __forceinline__ void ldsm4(uint32_t* r, uint32_t a) {
    asm volatile("ldmatrix.sync.aligned.m8n8.x4.shared.b16 {%0,%1,%2,%3}, [%4];"
                 : "=r"(r[0]), "=r"(r[1]), "=r"(r[2]), "=r"(r[3]) : "r"(a));
}
__device__ __forceinline__ void ldsm4t(uint32_t* r, uint32_t a) {
    asm volatile("ldmatrix.sync.aligned.m8n8.x4.trans.shared.b16 {%0,%1,%2,%3}, [%4];"
                 : "=r"(r[0]), "=r"(r[1]), "=r"(r[2]), "=r"(r[3]) : "r"(a));
}
__device__ __forceinline__ void mma_bf16(float* c, const uint32_t* a, const uint32_t* b) {
    asm volatile("mma.sync.aligned.m16n8k16.row.col.f32.bf16.bf16.f32 "
                 "{%0,%1,%2,%3}, {%4,%5,%6,%7}, {%8,%9}, {%0,%1,%2,%3};"
                 : "+f"(c[0]), "+f"(c[1]), "+f"(c[2]), "+f"(c[3])
                 : "r"(a[0]), "r"(a[1]), "r"(a[2]), "r"(a[3]), "r"(b[0]), "r"(b[1]));
}
__device__ __forceinline__ uint32_t cvt2(float lo, float hi) {
    uint32_t r;
    asm("cvt.rn.satfinite.bf16x2.f32 %0, %1, %2;" : "=r"(r) : "f"(hi), "f"(lo));
    return r;
}
__device__ __forceinline__ void split2(float x, float y, uint32_t& hi, uint32_t& lo) {
    hi = cvt2(x, y);
    float hx = __uint_as_float(hi << 16);
    float hy = __uint_as_float(hi & 0xffff0000u);
    lo = cvt2(x - hx, y - hy);
}
#define CP16(dst, src) asm volatile("cp.async.cg.shared.global [%0], [%1], 16;" :: "r"(dst), "l"(src))
#define CP_COMMIT()    asm volatile("cp.async.commit_group;")
#define CP_WAIT0()     asm volatile("cp.async.wait_group 0;" ::: "memory")
#define CP_WAIT1()     asm volatile("cp.async.wait_group 1;" ::: "memory")

// ---------------------------------------------------------------------------
__global__ void k_prep(const float* __restrict__ W) {
    int t = blockIdx.x * blockDim.x + threadIdx.x;
    if (t < B_ * K_) { g_ssum[t] = 0.f; g_colss[t] = 0.f; }
    if (t < K_ * D_ / 4) {
        float4 v = *(const float4*)&W[t * 4];
        uint32_t h0, l0, h1, l1;
        split2(v.x, v.y, h0, l0);
        split2(v.z, v.w, h1, l1);
        *(uint2*)&g_Wh[t * 4] = make_uint2(h0, h1);
        *(uint2*)&g_Wl[t * 4] = make_uint2(l0, l1);
    }
}

// ---------------------------------------------------------------------------
// Kernel A: logits[64 k][128 n] = W @ x_tile (reduce D=512), hi/lo 3-pass MMA.
// W planes via cp.async; x converted in-regs and ALSO written out as planes.
#define PA 40
#define PX 136
#define A_BUF  27648
#define A_ST2H 34048
#define A_ST2L 50432
#define A_SMEM (50432 + 16384)

__global__ __launch_bounds__(256) void kA(const float* __restrict__ x) {
    extern __shared__ char sm[];
    const int b = blockIdx.y, n0 = blockIdx.x * 128;
    const int tid = threadIdx.x, lane = tid & 31, wid = tid >> 5;
    const int wm = wid & 3, wn = wid >> 2;
    const uint32_t smb = smem_u32(sm);

    const int wk2 = tid >> 2, wd8 = (tid & 3) * 8;   // W cp.async: k row, d offset(8)
    const int xnn = lane * 4;                         // x: n offset

    float acc[8][4];
#pragma unroll
    for (int i = 0; i < 8; i++)
#pragma unroll
        for (int j = 0; j < 4; j++) acc[i][j] = 0.f;

    {
        uint32_t dst = smb + wk2 * 80 + wd8 * 2;
        CP16(dst,        &g_Wh[wk2 * D_ + wd8]);
        CP16(dst + 5120, &g_Wl[wk2 * D_ + wd8]);
        CP_COMMIT();
    }
    float4 xbuf[4];
#pragma unroll
    for (int p = 0; p < 4; p++)
        xbuf[p] = *(const float4*)&x[((size_t)b * D_ + wid + p * 8) * N_ + n0 + xnn];

    for (int c = 0; c < 16; c++) {
        char* bufc = sm + (c & 1) * A_BUF;
        __nv_bfloat16* Xh = (__nv_bfloat16*)(bufc + 10240);
        __nv_bfloat16* Xl = (__nv_bfloat16*)(bufc + 18944);
        const int d0c = c * 32;

        // split x chunk: store to smem AND to global planes (single conversion site)
#pragma unroll
        for (int p = 0; p < 4; p++) {
            int dd = wid + p * 8;
            uint32_t h0, l0, h1, l1;
            split2(xbuf[p].x, xbuf[p].y, h0, l0);
            split2(xbuf[p].z, xbuf[p].w, h1, l1);
            int off = dd * PX + xnn;
            *(uint32_t*)&Xh[off] = h0; *(uint32_t*)&Xh[off + 2] = h1;
            *(uint32_t*)&Xl[off] = l0; *(uint32_t*)&Xl[off + 2] = l1;
            size_t gx = ((size_t)b * D_ + d0c + dd) * N_ + n0 + xnn;
            *(uint2*)&g_Xh[gx] = make_uint2(h0, h1);
            *(uint2*)&g_Xl[gx] = make_uint2(l0, l1);
        }
        CP_WAIT0();
        __syncthreads();

        if (c < 15) {
            int d1 = (c + 1) * 32;
            uint32_t dst = smb + ((c + 1) & 1) * A_BUF + wk2 * 80 + wd8 * 2;
            CP16(dst,        &g_Wh[wk2 * D_ + d1 + wd8]);
            CP16(dst + 5120, &g_Wl[wk2 * D_ + d1 + wd8]);
            CP_COMMIT();
#pragma unroll
            for (int p = 0; p < 4; p++)
                xbuf[p] = *(const float4*)&x[((size_t)b * D_ + d1 + wid + p * 8) * N_ + n0 + xnn];
        }

        const uint32_t wh_a = smb + (c & 1) * A_BUF;
        const uint32_t wl_a = wh_a + 5120;
        const uint32_t xh_a = wh_a + 10240;
        const uint32_t xl_a = wh_a + 18944;
#pragma unroll
        for (int ks = 0; ks < 2; ks++) {
            uint32_t ah[4], al[4];
            uint32_t aoff = (uint32_t)(((wm * 16 + (lane & 15)) * PA + ks * 16 + (lane >> 4) * 8) * 2);
            ldsm4(ah, wh_a + aoff);
            ldsm4(al, wl_a + aoff);
#pragma unroll
            for (int nf = 0; nf < 4; nf++) {
                uint32_t bh[4], bl[4];
                uint32_t boff = (uint32_t)(((ks * 16 + (lane & 15)) * PX +
                                            wn * 64 + nf * 16 + (lane >> 4) * 8) * 2);
                ldsm4t(bh, xh_a + boff);
                ldsm4t(bl, xl_a + boff);
                mma_bf16(acc[nf * 2],     ah, bh);
                mma_bf16(acc[nf * 2],     ah, bl);
                mma_bf16(acc[nf * 2],     al, bh);
                mma_bf16(acc[nf * 2 + 1], ah, bh + 2);
                mma_bf16(acc[nf * 2 + 1], ah, bl + 2);
                mma_bf16(acc[nf * 2 + 1], al, bh + 2);
            }
        }
    }
    __syncthreads();

    // stash logits tile [64][132] f32
    float* st = (float*)sm;
    {
        int g = lane >> 2, tg = lane & 3;
        int r0 = wm * 16 + g;
#pragma unroll
        for (int nf = 0; nf < 8; nf++) {
            int cix = wn * 64 + nf * 8 + tg * 2;
            st[r0 * 132 + cix]           = acc[nf][0];
            st[r0 * 132 + cix + 1]       = acc[nf][1];
            st[(r0 + 8) * 132 + cix]     = acc[nf][2];
            st[(r0 + 8) * 132 + cix + 1] = acc[nf][3];
        }
    }
    float* ssred = (float*)(sm + 33792);
    __nv_bfloat16* st2h = (__nv_bfloat16*)(sm + A_ST2H);
    __nv_bfloat16* st2l = (__nv_bfloat16*)(sm + A_ST2L);
    if (tid < 64) ssred[tid] = 0.f;
    __syncthreads();

    // softmax over k per column
    if (tid < 128) {
        int col = tid;
        float m = -1e30f;
#pragma unroll
        for (int k = 0; k < 64; k++) m = fmaxf(m, st[k * 132 + col]);
        float s = 0.f;
#pragma unroll
        for (int k = 0; k < 64; k++) {
            float e = __expf(st[k * 132 + col] - m);
            st[k * 132 + col] = e;
            s += e;
        }
        float inv = 1.f / s;
#pragma unroll
        for (int k = 0; k < 64; k++) {
            float v = st[k * 132 + col] * inv;
            __nv_bfloat16 h = __float2bfloat16(v);
            float r = v - __bfloat162float(h);
            st2h[k * 128 + col] = h;
            st2l[k * 128 + col] = __float2bfloat16(r);
            float ws = v;
#pragma unroll
            for (int o = 16; o > 0; o >>= 1) ws += __shfl_xor_sync(0xffffffff, ws, o);
            if (lane == 0) atomicAdd(&ssred[k], ws);
        }
    }
    __syncthreads();

    // coalesced plane writes
#pragma unroll
    for (int r = 0; r < 8; r++) {
        int row = wid * 8 + r;
        size_t goff = ((size_t)b * K_ + row) * N_ + n0;
        uint2 vh = ((const uint2*)&st2h[row * 128])[lane];
        uint2 vl = ((const uint2*)&st2l[row * 128])[lane];
        ((uint2*)&g_Sh[goff])[lane] = vh;
        ((uint2*)&g_Sl[goff])[lane] = vl;
    }
    if (tid < 64) atomicAdd(&g_ssum[b * K_ + tid], ssred[tid]);
}

// ---------------------------------------------------------------------------
// Kernel B: agg_part[sp][128 d][64 k] = x @ scores^T (reduce 512 n).
// Pure cp.async: both operands stream as pre-split bf16 planes. 3-stage ring,
// one sync per chunk, no conversion ALU at all.
#define PB 40
#define B_BUF  30720
#define B_SMEM (3 * B_BUF)

__global__ __launch_bounds__(256) void kB() {
    extern __shared__ char sm[];
    const int b = blockIdx.y;
    const int d0 = (blockIdx.x & 3) * 128;
    const int sp = blockIdx.x >> 2;
    const int spn = sp * 512;
    const int tid = threadIdx.x, lane = tid & 31, wid = tid >> 5;
    const uint32_t smb = smem_u32(sm);

    // cp.async assignments
    const int xr = tid >> 1, xh2 = (tid & 1) * 32;   // X planes: row, 32B half
    const int sr = tid >> 2, sq = (tid & 3) * 16;    // S planes: row, 16B quarter
    const size_t gx_base = ((size_t)b * D_ + d0 + xr) * N_ + spn;
    const size_t gs_base = ((size_t)b * K_ + sr) * N_ + spn;

    float acc[8][4];
#pragma unroll
    for (int i = 0; i < 8; i++)
#pragma unroll
        for (int j = 0; j < 4; j++) acc[i][j] = 0.f;

#define KB_ISSUE(c)                                                          \
    do {                                                                     \
        uint32_t buf = smb + ((c) % 3) * B_BUF;                              \
        int nn = (c) * 32;                                                   \
        const char* pxh = (const char*)&g_Xh[gx_base + nn] + xh2;            \
        const char* pxl = (const char*)&g_Xl[gx_base + nn] + xh2;            \
        uint32_t dx = buf + xr * 80 + xh2;                                   \
        CP16(dx, pxh); CP16(dx + 16, pxh + 16);                              \
        CP16(dx + 10240, pxl); CP16(dx + 10240 + 16, pxl + 16);              \
        const char* psh = (const char*)&g_Sh[gs_base + nn] + sq;             \
        const char* psl = (const char*)&g_Sl[gs_base + nn] + sq;             \
        uint32_t ds = buf + 20480 + sr * 80 + sq;                            \
        CP16(ds, psh);                                                       \
        CP16(ds + 5120, psl);                                                \
        CP_COMMIT();                                                         \
    } while (0)

    KB_ISSUE(0);
    KB_ISSUE(1);

    for (int c = 0; c < 16; c++) {
        if (c < 15) { CP_WAIT1(); } else { CP_WAIT0(); }
        __syncthreads();
        if (c < 14) KB_ISSUE(c + 2);

        const uint32_t xh_a = smb + (c % 3) * B_BUF;
        const uint32_t xl_a = xh_a + 10240;
        const uint32_t sh_a = xh_a + 20480;
        const uint32_t sl_a = xh_a + 25600;
#pragma unroll
        for (int ks = 0; ks < 2; ks++) {
            uint32_t ah[4], al[4];
            uint32_t aoff = (uint32_t)(((wid * 16 + (lane & 15)) * PB + ks * 16 + (lane >> 4) * 8) * 2);
            ldsm4(ah, xh_a + aoff);
            ldsm4(al, xl_a + aoff);
#pragma unroll
            for (int nf = 0; nf < 4; nf++) {
                uint32_t bh[4], bl[4];
                uint32_t boff = (uint32_t)(((nf * 16 + (lane & 7) + ((lane >> 4) << 3)) * PB +
                                            ks * 16 + ((lane >> 3) & 1) * 8) * 2);
                ldsm4(bh, sh_a + boff);
                ldsm4(bl, sl_a + boff);
                mma_bf16(acc[nf * 2],     ah, bh);
                mma_bf16(acc[nf * 2],     ah, bl);
                mma_bf16(acc[nf * 2],     al, bh);
                mma_bf16(acc[nf * 2 + 1], ah, bh + 2);
                mma_bf16(acc[nf * 2 + 1], ah, bl + 2);
                mma_bf16(acc[nf * 2 + 1], al, bh + 2);
            }
        }
    }
#undef KB_ISSUE

    int g = lane >> 2, tg = lane & 3;
    int d = d0 + wid * 16 + g;
    float* base = &g_aggp[sp][((size_t)b * D_ + d) * K_];
#pragma unroll
    for (int nf = 0; nf < 8; nf++) {
        int cix = nf * 8 + tg * 2;
        base[cix]              = acc[nf][0];
        base[cix + 1]          = acc[nf][1];
        base[8 * K_ + cix]     = acc[nf][2];
        base[8 * K_ + cix + 1] = acc[nf][3];
    }
}

// ---------------------------------------------------------------------------
// Epilogue
__global__ __launch_bounds__(256) void k_colss(const float* __restrict__ centers) {
    const int b = blockIdx.y, d0 = blockIdx.x * 32;
    const int tid = threadIdx.x;
    const int k = tid & 63, dg = tid >> 6;
    __shared__ float red[4][64];
    const float ssumk = g_ssum[b * K_ + k];
    float acc = 0.f;
#pragma unroll
    for (int t = 0; t < 8; t++) {
        int d = d0 + dg + t * 4;
        size_t idx = (size_t)b * D_ * K_ + (size_t)d * K_ + k;
        float v = g_aggp[0][idx] + g_aggp[1][idx] + g_aggp[2][idx] + g_aggp[3][idx]
                  - centers[d * K_ + k] * ssumk;
        g_aggp[0][idx] = v;
        acc = fmaf(v, v, acc);
    }
    red[dg][k] = acc;
    __syncthreads();
    if (tid < 64) {
        float tot = red[0][tid] + red[1][tid] + red[2][tid] + red[3][tid];
        atomicAdd(&g_colss[b * K_ + tid], tot);
    }
}

__global__ void k_mult() {
    const int b = blockIdx.x, k = threadIdx.x;
    __shared__ float sh[64];
    float ss = g_colss[b * K_ + k];
    float m = fmaxf(sqrtf(ss), 1e-12f);
    sh[k] = ss / (m * m);
    __syncthreads();
    for (int o = 32; o > 0; o >>= 1) {
        if (k < o) sh[k] += sh[k + o];
        __syncthreads();
    }
    float scale2 = 1.f / fmaxf(sqrtf(sh[0]), 1e-12f);
    g_mult[b * K_ + k] = scale2 / m;
}

__global__ __launch_bounds__(256) void k_out(float* __restrict__ out) {
    const int b = blockIdx.y, d0 = blockIdx.x * 32;
    const int tid = threadIdx.x;
    const int k = tid & 63, dg = tid >> 6;
    const float mult = g_mult[b * K_ + k];
    float* op = &out[(size_t)b * D_ * K_];
#pragma unroll
    for (int t = 0; t < 8; t++) {
        int d = d0 + dg + t * 4;
        size_t idx = (size_t)b * D_ * K_ + (size_t)d * K_ + k;
        op[d * K_ + k] = g_aggp[0][idx] * mult;
    }
}

// ---------------------------------------------------------------------------
extern "C" void kernel_launch(void* const* d_in, const int* in_sizes, int n_in,
                              void* d_out, int out_size) {
    const float* x       = (const float*)d_in[0];  // [B, D, N]
    const float* W       = (const float*)d_in[1];  // [K, D]
    const float* centers = (const float*)d_in[2];  // [D, K]
    float* out = (float*)d_out;                    // [B, D*K]

    cudaFuncSetAttribute(kA, cudaFuncAttributeMaxDynamicSharedMemorySize, A_SMEM);
    cudaFuncSetAttribute(kB, cudaFuncAttributeMaxDynamicSharedMemorySize, B_SMEM);

    k_prep<<<32, 256>>>(W);
    dim3 gA(N_ / 128, B_);
    kA<<<gA, 256, A_SMEM>>>(x);
    dim3 gB(16, B_);           // 4 d-tiles x 4 n-splits
    kB<<<gB, 256, B_SMEM>>>();
    dim3 gE(D_ / 32, B_);
    k_colss<<<gE, 256>>>(centers);
    k_mult<<<B_, 64>>>();
    k_out<<<gE, 256>>>(out);
}

// round 9
// speedup vs baseline: 1.2610x; 1.2610x over previous
#include <cuda_runtime.h>
#include <cuda_bf16.h>
#include <cuda_fp16.h>
#include <math.h>
#include <stdint.h>

#define B_ 32
#define D_ 512
#define N_ 2048
#define K_ 64

// ---------------------------------------------------------------------------
// Scratch (static device globals; no allocations allowed)
__device__ __align__(16) __nv_bfloat16 g_Wh[K_ * D_];               // W hi plane (bf16)
__device__ __align__(16) __nv_bfloat16 g_Wl[K_ * D_];               // W lo plane (bf16)
__device__ __align__(16) __half g_Sf[(size_t)B_ * K_ * N_];         // scores fp16 (8 MB)
__device__ __align__(16) float g_ssum[B_ * K_];
__device__ __align__(16) float g_aggp[4][(size_t)B_ * D_ * K_];     // split-K parts
__device__ __align__(16) float g_colss[B_ * K_];
__device__ __align__(16) float g_mult[B_ * K_];

// ---------------------------------------------------------------------------
__device__ __forceinline__ uint32_t smem_u32(const void* p) {
    uint32_t a;
    asm("{ .reg .u64 t; cvta.to.shared.u64 t, %1; cvt.u32.u64 %0, t; }" : "=r"(a) : "l"(p));
    return a;
}
__device__ __forceinline__ void ldsm4(uint32_t* r, uint32_t a) {
    asm volatile("ldmatrix.sync.aligned.m8n8.x4.shared.b16 {%0,%1,%2,%3}, [%4];"
                 : "=r"(r[0]), "=r"(r[1]), "=r"(r[2]), "=r"(r[3]) : "r"(a));
}
__device__ __forceinline__ void ldsm4t(uint32_t* r, uint32_t a) {
    asm volatile("ldmatrix.sync.aligned.m8n8.x4.trans.shared.b16 {%0,%1,%2,%3}, [%4];"
                 : "=r"(r[0]), "=r"(r[1]), "=r"(r[2]), "=r"(r[3]) : "r"(a));
}
__device__ __forceinline__ void mma_bf16(float* c, const uint32_t* a, const uint32_t* b) {
    asm volatile("mma.sync.aligned.m16n8k16.row.col.f32.bf16.bf16.f32 "
                 "{%0,%1,%2,%3}, {%4,%5,%6,%7}, {%8,%9}, {%0,%1,%2,%3};"
                 : "+f"(c[0]), "+f"(c[1]), "+f"(c[2]), "+f"(c[3])
                 : "r"(a[0]), "r"(a[1]), "r"(a[2]), "r"(a[3]), "r"(b[0]), "r"(b[1]));
}
__device__ __forceinline__ void mma_f16(float* c, const uint32_t* a, const uint32_t* b) {
    asm volatile("mma.sync.aligned.m16n8k16.row.col.f32.f16.f16.f32 "
                 "{%0,%1,%2,%3}, {%4,%5,%6,%7}, {%8,%9}, {%0,%1,%2,%3};"
                 : "+f"(c[0]), "+f"(c[1]), "+f"(c[2]), "+f"(c[3])
                 : "r"(a[0]), "r"(a[1]), "r"(a[2]), "r"(a[3]), "r"(b[0]), "r"(b[1]));
}
__device__ __forceinline__ uint32_t cvt2(float lo, float hi) {
    uint32_t r;
    asm("cvt.rn.satfinite.bf16x2.f32 %0, %1, %2;" : "=r"(r) : "f"(hi), "f"(lo));
    return r;
}
// bf16 hi/lo split (for kA / W)
__device__ __forceinline__ void split2(float x, float y, uint32_t& hi, uint32_t& lo) {
    hi = cvt2(x, y);
    float hx = __uint_as_float(hi << 16);
    float hy = __uint_as_float(hi & 0xffff0000u);
    lo = cvt2(x - hx, y - hy);
}
// fp16 hi/lo split (for kB x operand)
__device__ __forceinline__ void split2h(float x, float y, uint32_t& hi, uint32_t& lo) {
    __half2 h = __floats2half2_rn(x, y);
    float2 f = __half22float2(h);
    __half2 l = __floats2half2_rn(x - f.x, y - f.y);
    hi = *(uint32_t*)&h;
    lo = *(uint32_t*)&l;
}
#define CP16(dst, src) asm volatile("cp.async.cg.shared.global [%0], [%1], 16;" :: "r"(dst), "l"(src))
#define CP_COMMIT()    asm volatile("cp.async.commit_group;")
#define CP_WAIT0()     asm volatile("cp.async.wait_group 0;" ::: "memory")

// ---------------------------------------------------------------------------
__global__ void k_prep(const float* __restrict__ W) {
    int t = blockIdx.x * blockDim.x + threadIdx.x;
    if (t < B_ * K_) { g_ssum[t] = 0.f; g_colss[t] = 0.f; }
    if (t < K_ * D_ / 4) {
        float4 v = *(const float4*)&W[t * 4];
        uint32_t h0, l0, h1, l1;
        split2(v.x, v.y, h0, l0);
        split2(v.z, v.w, h1, l1);
        *(uint2*)&g_Wh[t * 4] = make_uint2(h0, h1);
        *(uint2*)&g_Wl[t * 4] = make_uint2(l0, l1);
    }
}

// ---------------------------------------------------------------------------
// Kernel A: logits[64 k][128 n] = W @ x_tile (reduce D=512), bf16 hi/lo 3-pass.
// W planes via cp.async; x converted in-regs. Fused softmax -> fp16 scores.
#define PA 40
#define PX 136
#define A_BUF  27648
#define A_ST2  34048
#define A_SMEM (2 * A_BUF)

__global__ __launch_bounds__(256) void kA(const float* __restrict__ x) {
    extern __shared__ char sm[];
    const int b = blockIdx.y, n0 = blockIdx.x * 128;
    const int tid = threadIdx.x, lane = tid & 31, wid = tid >> 5;
    const int wm = wid & 3, wn = wid >> 2;
    const uint32_t smb = smem_u32(sm);

    const int wk2 = tid >> 2, wd8 = (tid & 3) * 8;   // W cp.async: k row, d offset(8)
    const int xnn = lane * 4;                         // x: n offset

    float acc[8][4];
#pragma unroll
    for (int i = 0; i < 8; i++)
#pragma unroll
        for (int j = 0; j < 4; j++) acc[i][j] = 0.f;

    {
        uint32_t dst = smb + wk2 * 80 + wd8 * 2;
        CP16(dst,        &g_Wh[wk2 * D_ + wd8]);
        CP16(dst + 5120, &g_Wl[wk2 * D_ + wd8]);
        CP_COMMIT();
    }
    float4 xbuf[4];
#pragma unroll
    for (int p = 0; p < 4; p++)
        xbuf[p] = *(const float4*)&x[((size_t)b * D_ + wid + p * 8) * N_ + n0 + xnn];

    for (int c = 0; c < 16; c++) {
        char* bufc = sm + (c & 1) * A_BUF;
        __nv_bfloat16* Xh = (__nv_bfloat16*)(bufc + 10240);
        __nv_bfloat16* Xl = (__nv_bfloat16*)(bufc + 18944);

#pragma unroll
        for (int p = 0; p < 4; p++) {
            int dd = wid + p * 8;
            uint32_t h0, l0, h1, l1;
            split2(xbuf[p].x, xbuf[p].y, h0, l0);
            split2(xbuf[p].z, xbuf[p].w, h1, l1);
            int off = dd * PX + xnn;
            *(uint32_t*)&Xh[off] = h0; *(uint32_t*)&Xh[off + 2] = h1;
            *(uint32_t*)&Xl[off] = l0; *(uint32_t*)&Xl[off + 2] = l1;
        }
        CP_WAIT0();
        __syncthreads();

        if (c < 15) {
            int d1 = (c + 1) * 32;
            uint32_t dst = smb + ((c + 1) & 1) * A_BUF + wk2 * 80 + wd8 * 2;
            CP16(dst,        &g_Wh[wk2 * D_ + d1 + wd8]);
            CP16(dst + 5120, &g_Wl[wk2 * D_ + d1 + wd8]);
            CP_COMMIT();
#pragma unroll
            for (int p = 0; p < 4; p++)
                xbuf[p] = *(const float4*)&x[((size_t)b * D_ + d1 + wid + p * 8) * N_ + n0 + xnn];
        }

        const uint32_t wh_a = smb + (c & 1) * A_BUF;
        const uint32_t wl_a = wh_a + 5120;
        const uint32_t xh_a = wh_a + 10240;
        const uint32_t xl_a = wh_a + 18944;
#pragma unroll
        for (int ks = 0; ks < 2; ks++) {
            uint32_t ah[4], al[4];
            uint32_t aoff = (uint32_t)(((wm * 16 + (lane & 15)) * PA + ks * 16 + (lane >> 4) * 8) * 2);
            ldsm4(ah, wh_a + aoff);
            ldsm4(al, wl_a + aoff);
#pragma unroll
            for (int nf = 0; nf < 4; nf++) {
                uint32_t bh[4], bl[4];
                uint32_t boff = (uint32_t)(((ks * 16 + (lane & 15)) * PX +
                                            wn * 64 + nf * 16 + (lane >> 4) * 8) * 2);
                ldsm4t(bh, xh_a + boff);
                ldsm4t(bl, xl_a + boff);
                mma_bf16(acc[nf * 2],     ah, bh);
                mma_bf16(acc[nf * 2],     ah, bl);
                mma_bf16(acc[nf * 2],     al, bh);
                mma_bf16(acc[nf * 2 + 1], ah, bh + 2);
                mma_bf16(acc[nf * 2 + 1], ah, bl + 2);
                mma_bf16(acc[nf * 2 + 1], al, bh + 2);
            }
        }
    }
    __syncthreads();

    // stash logits tile [64][132] f32
    float* st = (float*)sm;
    {
        int g = lane >> 2, tg = lane & 3;
        int r0 = wm * 16 + g;
#pragma unroll
        for (int nf = 0; nf < 8; nf++) {
            int cix = wn * 64 + nf * 8 + tg * 2;
            st[r0 * 132 + cix]           = acc[nf][0];
            st[r0 * 132 + cix + 1]       = acc[nf][1];
            st[(r0 + 8) * 132 + cix]     = acc[nf][2];
            st[(r0 + 8) * 132 + cix + 1] = acc[nf][3];
        }
    }
    float* ssred = (float*)(sm + 33792);
    __half* st2 = (__half*)(sm + A_ST2);
    if (tid < 64) ssred[tid] = 0.f;
    __syncthreads();

    // softmax over k per column; quantize scores to fp16 (self-consistent ssum)
    if (tid < 128) {
        int col = tid;
        float m = -1e30f;
#pragma unroll
        for (int k = 0; k < 64; k++) m = fmaxf(m, st[k * 132 + col]);
        float s = 0.f;
#pragma unroll
        for (int k = 0; k < 64; k++) {
            float e = __expf(st[k * 132 + col] - m);
            st[k * 132 + col] = e;
            s += e;
        }
        float inv = 1.f / s;
#pragma unroll
        for (int k = 0; k < 64; k++) {
            __half h = __float2half_rn(st[k * 132 + col] * inv);
            st2[k * 128 + col] = h;
            float ws = __half2float(h);
#pragma unroll
            for (int o = 16; o > 0; o >>= 1) ws += __shfl_xor_sync(0xffffffff, ws, o);
            if (lane == 0) atomicAdd(&ssred[k], ws);
        }
    }
    __syncthreads();

    // coalesced fp16 score writes: warp w -> rows w*8..+7, uint2 (4 halfs)/thread
#pragma unroll
    for (int r = 0; r < 8; r++) {
        int row = wid * 8 + r;
        uint2 v = ((const uint2*)&st2[row * 128])[lane];
        ((uint2*)&g_Sf[((size_t)b * K_ + row) * N_ + n0])[lane] = v;
    }
    if (tid < 64) atomicAdd(&g_ssum[b * K_ + tid], ssred[tid]);
}

// ---------------------------------------------------------------------------
// Kernel B: agg_part[sp][128 d][64 k] = x @ s^T (reduce 512 n), fp16 2-pass:
// acc += x_hi*s + x_lo*s. Scores via cp.async, x split in-regs. Split-K 4.
// smem per stage: Xh 10240 | Xl 10240 | S 5120 = 25600; x2 stages.
#define PB 40
#define B_BUF  25600
#define B_SMEM (2 * B_BUF)

__global__ __launch_bounds__(256) void kB(const float* __restrict__ x) {
    extern __shared__ char sm[];
    const int b = blockIdx.y;
    const int d0 = (blockIdx.x & 3) * 128;
    const int sp = blockIdx.x >> 2;
    const int spn = sp * 512;
    const int tid = threadIdx.x, lane = tid & 31, wid = tid >> 5;
    const uint32_t smb = smem_u32(sm);

    const int xrr = tid >> 3, xnn = (tid & 7) * 4;   // x: d row base, n offset
    const int sr = tid >> 2, sq = (tid & 3) * 16;    // S cp.async: row, 16B quarter
    const size_t gs_base = ((size_t)b * K_ + sr) * N_ + spn;

    float acc[8][4];
#pragma unroll
    for (int i = 0; i < 8; i++)
#pragma unroll
        for (int j = 0; j < 4; j++) acc[i][j] = 0.f;

    {
        uint32_t dst = smb + 20480 + sr * 80 + sq;
        CP16(dst, (const char*)&g_Sf[gs_base] + sq);
        CP_COMMIT();
    }
    float4 xbuf[4];
#pragma unroll
    for (int p = 0; p < 4; p++)
        xbuf[p] = *(const float4*)&x[((size_t)b * D_ + d0 + xrr + p * 32) * N_ + spn + xnn];

    for (int c = 0; c < 16; c++) {
        char* bufc = sm + (c & 1) * B_BUF;
        __half* Xh = (__half*)(bufc);
        __half* Xl = (__half*)(bufc + 10240);

#pragma unroll
        for (int p = 0; p < 4; p++) {
            int rr = xrr + p * 32;
            uint32_t h0, l0, h1, l1;
            split2h(xbuf[p].x, xbuf[p].y, h0, l0);
            split2h(xbuf[p].z, xbuf[p].w, h1, l1);
            int off = rr * PB + xnn;
            *(uint32_t*)&Xh[off] = h0; *(uint32_t*)&Xh[off + 2] = h1;
            *(uint32_t*)&Xl[off] = l0; *(uint32_t*)&Xl[off + 2] = l1;
        }
        CP_WAIT0();
        __syncthreads();

        if (c < 15) {
            int n1 = (c + 1) * 32;
            uint32_t dst = smb + ((c + 1) & 1) * B_BUF + 20480 + sr * 80 + sq;
            CP16(dst, (const char*)&g_Sf[gs_base + n1] + sq);
            CP_COMMIT();
#pragma unroll
            for (int p = 0; p < 4; p++)
                xbuf[p] = *(const float4*)&x[((size_t)b * D_ + d0 + xrr + p * 32) * N_ + spn + n1 + xnn];
        }

        const uint32_t xh_a = smb + (c & 1) * B_BUF;
        const uint32_t xl_a = xh_a + 10240;
        const uint32_t s_a  = xh_a + 20480;
#pragma unroll
        for (int ks = 0; ks < 2; ks++) {
            uint32_t ah[4], al[4];
            uint32_t aoff = (uint32_t)(((wid * 16 + (lane & 15)) * PB + ks * 16 + (lane >> 4) * 8) * 2);
            ldsm4(ah, xh_a + aoff);
            ldsm4(al, xl_a + aoff);
#pragma unroll
            for (int nf = 0; nf < 4; nf++) {
                uint32_t bh[4];
                uint32_t boff = (uint32_t)(((nf * 16 + (lane & 7) + ((lane >> 4) << 3)) * PB +
                                            ks * 16 + ((lane >> 3) & 1) * 8) * 2);
                ldsm4(bh, s_a + boff);
                mma_f16(acc[nf * 2],     ah, bh);
                mma_f16(acc[nf * 2],     al, bh);
                mma_f16(acc[nf * 2 + 1], ah, bh + 2);
                mma_f16(acc[nf * 2 + 1], al, bh + 2);
            }
        }
    }

    int g = lane >> 2, tg = lane & 3;
    int d = d0 + wid * 16 + g;
    float* base = &g_aggp[sp][((size_t)b * D_ + d) * K_];
#pragma unroll
    for (int nf = 0; nf < 8; nf++) {
        int cix = nf * 8 + tg * 2;
        base[cix]              = acc[nf][0];
        base[cix + 1]          = acc[nf][1];
        base[8 * K_ + cix]     = acc[nf][2];
        base[8 * K_ + cix + 1] = acc[nf][3];
    }
}

// ---------------------------------------------------------------------------
// Epilogue
__global__ __launch_bounds__(256) void k_colss(const float* __restrict__ centers) {
    const int b = blockIdx.y, d0 = blockIdx.x * 32;
    const int tid = threadIdx.x;
    const int k = tid & 63, dg = tid >> 6;
    __shared__ float red[4][64];
    const float ssumk = g_ssum[b * K_ + k];
    float acc = 0.f;
#pragma unroll
    for (int t = 0; t < 8; t++) {
        int d = d0 + dg + t * 4;
        size_t idx = (size_t)b * D_ * K_ + (size_t)d * K_ + k;
        float v = g_aggp[0][idx] + g_aggp[1][idx] + g_aggp[2][idx] + g_aggp[3][idx]
                  - centers[d * K_ + k] * ssumk;
        g_aggp[0][idx] = v;
        acc = fmaf(v, v, acc);
    }
    red[dg][k] = acc;
    __syncthreads();
    if (tid < 64) {
        float tot = red[0][tid] + red[1][tid] + red[2][tid] + red[3][tid];
        atomicAdd(&g_colss[b * K_ + tid], tot);
    }
}

__global__ void k_mult() {
    const int b = blockIdx.x, k = threadIdx.x;
    __shared__ float sh[64];
    float ss = g_colss[b * K_ + k];
    float m = fmaxf(sqrtf(ss), 1e-12f);
    sh[k] = ss / (m * m);
    __syncthreads();
    for (int o = 32; o > 0; o >>= 1) {
        if (k < o) sh[k] += sh[k + o];
        __syncthreads();
    }
    float scale2 = 1.f / fmaxf(sqrtf(sh[0]), 1e-12f);
    g_mult[b * K_ + k] = scale2 / m;
}

__global__ __launch_bounds__(256) void k_out(float* __restrict__ out) {
    const int b = blockIdx.y, d0 = blockIdx.x * 32;
    const int tid = threadIdx.x;
    const int k = tid & 63, dg = tid >> 6;
    const float mult = g_mult[b * K_ + k];
    float* op = &out[(size_t)b * D_ * K_];
#pragma unroll
    for (int t = 0; t < 8; t++) {
        int d = d0 + dg + t * 4;
        size_t idx = (size_t)b * D_ * K_ + (size_t)d * K_ + k;
        op[d * K_ + k] = g_aggp[0][idx] * mult;
    }
}

// ---------------------------------------------------------------------------
extern "C" void kernel_launch(void* const* d_in, const int* in_sizes, int n_in,
                              void* d_out, int out_size) {
    const float* x       = (const float*)d_in[0];  // [B, D, N]
    const float* W       = (const float*)d_in[1];  // [K, D]
    const float* centers = (const float*)d_in[2];  // [D, K]
    float* out = (float*)d_out;                    // [B, D*K]

    cudaFuncSetAttribute(kA, cudaFuncAttributeMaxDynamicSharedMemorySize, A_SMEM);
    cudaFuncSetAttribute(kB, cudaFuncAttributeMaxDynamicSharedMemorySize, B_SMEM);

    k_prep<<<32, 256>>>(W);
    dim3 gA(N_ / 128, B_);
    kA<<<gA, 256, A_SMEM>>>(x);
    dim3 gB(16, B_);           // 4 d-tiles x 4 n-splits
    kB<<<gB, 256, B_SMEM>>>(x);
    dim3 gE(D_ / 32, B_);
    k_colss<<<gE, 256>>>(centers);
    k_mult<<<B_, 64>>>();
    k_out<<<gE, 256>>>(out);
}

// round 10
// speedup vs baseline: 1.4729x; 1.1681x over previous
#include <cuda_runtime.h>
#include <cuda_bf16.h>
#include <cuda_fp16.h>
#include <math.h>
#include <stdint.h>

#define B_ 32
#define D_ 512
#define N_ 2048
#define K_ 64

// ---------------------------------------------------------------------------
// Scratch (static device globals; no allocations allowed)
__device__ __align__(16) __nv_bfloat16 g_Wh[K_ * D_];               // W hi plane (bf16)
__device__ __align__(16) __nv_bfloat16 g_Wl[K_ * D_];               // W lo plane (bf16)
__device__ __align__(16) __half g_Sf[(size_t)B_ * K_ * N_];         // scores fp16 (8 MB)
__device__ __align__(16) float g_ssum[B_ * K_];
__device__ __align__(16) float g_aggp[4][(size_t)B_ * D_ * K_];     // split-K parts
__device__ __align__(16) float g_mult[B_ * K_];

// ---------------------------------------------------------------------------
__device__ __forceinline__ uint32_t smem_u32(const void* p) {
    uint32_t a;
    asm("{ .reg .u64 t; cvta.to.shared.u64 t, %1; cvt.u32.u64 %0, t; }" : "=r"(a) : "l"(p));
    return a;
}
__device__ __forceinline__ void ldsm4(uint32_t* r, uint32_t a) {
    asm volatile("ldmatrix.sync.aligned.m8n8.x4.shared.b16 {%0,%1,%2,%3}, [%4];"
                 : "=r"(r[0]), "=r"(r[1]), "=r"(r[2]), "=r"(r[3]) : "r"(a));
}
__device__ __forceinline__ void ldsm4t(uint32_t* r, uint32_t a) {
    asm volatile("ldmatrix.sync.aligned.m8n8.x4.trans.shared.b16 {%0,%1,%2,%3}, [%4];"
                 : "=r"(r[0]), "=r"(r[1]), "=r"(r[2]), "=r"(r[3]) : "r"(a));
}
__device__ __forceinline__ void mma_bf16(float* c, const uint32_t* a, const uint32_t* b) {
    asm volatile("mma.sync.aligned.m16n8k16.row.col.f32.bf16.bf16.f32 "
                 "{%0,%1,%2,%3}, {%4,%5,%6,%7}, {%8,%9}, {%0,%1,%2,%3};"
                 : "+f"(c[0]), "+f"(c[1]), "+f"(c[2]), "+f"(c[3])
                 : "r"(a[0]), "r"(a[1]), "r"(a[2]), "r"(a[3]), "r"(b[0]), "r"(b[1]));
}
__device__ __forceinline__ void mma_f16(float* c, const uint32_t* a, const uint32_t* b) {
    asm volatile("mma.sync.aligned.m16n8k16.row.col.f32.f16.f16.f32 "
                 "{%0,%1,%2,%3}, {%4,%5,%6,%7}, {%8,%9}, {%0,%1,%2,%3};"
                 : "+f"(c[0]), "+f"(c[1]), "+f"(c[2]), "+f"(c[3])
                 : "r"(a[0]), "r"(a[1]), "r"(a[2]), "r"(a[3]), "r"(b[0]), "r"(b[1]));
}
__device__ __forceinline__ uint32_t cvt2(float lo, float hi) {
    uint32_t r;
    asm("cvt.rn.satfinite.bf16x2.f32 %0, %1, %2;" : "=r"(r) : "f"(hi), "f"(lo));
    return r;
}
// bf16 hi/lo split (for kA / W)
__device__ __forceinline__ void split2(float x, float y, uint32_t& hi, uint32_t& lo) {
    hi = cvt2(x, y);
    float hx = __uint_as_float(hi << 16);
    float hy = __uint_as_float(hi & 0xffff0000u);
    lo = cvt2(x - hx, y - hy);
}
// fp16 hi/lo split (for kB x operand)
__device__ __forceinline__ void split2h(float x, float y, uint32_t& hi, uint32_t& lo) {
    __half2 h = __floats2half2_rn(x, y);
    float2 f = __half22float2(h);
    __half2 l = __floats2half2_rn(x - f.x, y - f.y);
    hi = *(uint32_t*)&h;
    lo = *(uint32_t*)&l;
}
#define CP16(dst, src) asm volatile("cp.async.cg.shared.global [%0], [%1], 16;" :: "r"(dst), "l"(src))
#define CP_COMMIT()    asm volatile("cp.async.commit_group;")
#define CP_WAIT0()     asm volatile("cp.async.wait_group 0;" ::: "memory")

// ---------------------------------------------------------------------------
__global__ void k_prep(const float* __restrict__ W) {
    int t = blockIdx.x * blockDim.x + threadIdx.x;
    if (t < B_ * K_) g_ssum[t] = 0.f;
    if (t < K_ * D_ / 4) {
        float4 v = *(const float4*)&W[t * 4];
        uint32_t h0, l0, h1, l1;
        split2(v.x, v.y, h0, l0);
        split2(v.z, v.w, h1, l1);
        *(uint2*)&g_Wh[t * 4] = make_uint2(h0, h1);
        *(uint2*)&g_Wl[t * 4] = make_uint2(l0, l1);
    }
}

// ---------------------------------------------------------------------------
// Kernel A: logits[64 k][128 n] = W @ x_tile (reduce D=512), bf16 hi/lo 3-pass.
// W planes via cp.async; x converted in-regs. Fused softmax -> fp16 scores.
// ssum computed from the quantized fp16 scores during the write-out loop.
#define PA 40
#define PX 136
#define A_BUF  27648
#define A_ST2  34048
#define A_SMEM (2 * A_BUF)

__global__ __launch_bounds__(256) void kA(const float* __restrict__ x) {
    extern __shared__ char sm[];
    const int b = blockIdx.y, n0 = blockIdx.x * 128;
    const int tid = threadIdx.x, lane = tid & 31, wid = tid >> 5;
    const int wm = wid & 3, wn = wid >> 2;
    const uint32_t smb = smem_u32(sm);

    const int wk2 = tid >> 2, wd8 = (tid & 3) * 8;   // W cp.async: k row, d offset(8)
    const int xnn = lane * 4;                         // x: n offset

    float acc[8][4];
#pragma unroll
    for (int i = 0; i < 8; i++)
#pragma unroll
        for (int j = 0; j < 4; j++) acc[i][j] = 0.f;

    {
        uint32_t dst = smb + wk2 * 80 + wd8 * 2;
        CP16(dst,        &g_Wh[wk2 * D_ + wd8]);
        CP16(dst + 5120, &g_Wl[wk2 * D_ + wd8]);
        CP_COMMIT();
    }
    float4 xbuf[4];
#pragma unroll
    for (int p = 0; p < 4; p++)
        xbuf[p] = *(const float4*)&x[((size_t)b * D_ + wid + p * 8) * N_ + n0 + xnn];

    for (int c = 0; c < 16; c++) {
        char* bufc = sm + (c & 1) * A_BUF;
        __nv_bfloat16* Xh = (__nv_bfloat16*)(bufc + 10240);
        __nv_bfloat16* Xl = (__nv_bfloat16*)(bufc + 18944);

#pragma unroll
        for (int p = 0; p < 4; p++) {
            int dd = wid + p * 8;
            uint32_t h0, l0, h1, l1;
            split2(xbuf[p].x, xbuf[p].y, h0, l0);
            split2(xbuf[p].z, xbuf[p].w, h1, l1);
            int off = dd * PX + xnn;
            *(uint32_t*)&Xh[off] = h0; *(uint32_t*)&Xh[off + 2] = h1;
            *(uint32_t*)&Xl[off] = l0; *(uint32_t*)&Xl[off + 2] = l1;
        }
        CP_WAIT0();
        __syncthreads();

        if (c < 15) {
            int d1 = (c + 1) * 32;
            uint32_t dst = smb + ((c + 1) & 1) * A_BUF + wk2 * 80 + wd8 * 2;
            CP16(dst,        &g_Wh[wk2 * D_ + d1 + wd8]);
            CP16(dst + 5120, &g_Wl[wk2 * D_ + d1 + wd8]);
            CP_COMMIT();
#pragma unroll
            for (int p = 0; p < 4; p++)
                xbuf[p] = *(const float4*)&x[((size_t)b * D_ + d1 + wid + p * 8) * N_ + n0 + xnn];
        }

        const uint32_t wh_a = smb + (c & 1) * A_BUF;
        const uint32_t wl_a = wh_a + 5120;
        const uint32_t xh_a = wh_a + 10240;
        const uint32_t xl_a = wh_a + 18944;
#pragma unroll
        for (int ks = 0; ks < 2; ks++) {
            uint32_t ah[4], al[4];
            uint32_t aoff = (uint32_t)(((wm * 16 + (lane & 15)) * PA + ks * 16 + (lane >> 4) * 8) * 2);
            ldsm4(ah, wh_a + aoff);
            ldsm4(al, wl_a + aoff);
#pragma unroll
            for (int nf = 0; nf < 4; nf++) {
                uint32_t bh[4], bl[4];
                uint32_t boff = (uint32_t)(((ks * 16 + (lane & 15)) * PX +
                                            wn * 64 + nf * 16 + (lane >> 4) * 8) * 2);
                ldsm4t(bh, xh_a + boff);
                ldsm4t(bl, xl_a + boff);
                mma_bf16(acc[nf * 2],     ah, bh);
                mma_bf16(acc[nf * 2],     ah, bl);
                mma_bf16(acc[nf * 2],     al, bh);
                mma_bf16(acc[nf * 2 + 1], ah, bh + 2);
                mma_bf16(acc[nf * 2 + 1], ah, bl + 2);
                mma_bf16(acc[nf * 2 + 1], al, bh + 2);
            }
        }
    }
    __syncthreads();

    // stash logits tile [64][132] f32
    float* st = (float*)sm;
    {
        int g = lane >> 2, tg = lane & 3;
        int r0 = wm * 16 + g;
#pragma unroll
        for (int nf = 0; nf < 8; nf++) {
            int cix = wn * 64 + nf * 8 + tg * 2;
            st[r0 * 132 + cix]           = acc[nf][0];
            st[r0 * 132 + cix + 1]       = acc[nf][1];
            st[(r0 + 8) * 132 + cix]     = acc[nf][2];
            st[(r0 + 8) * 132 + cix + 1] = acc[nf][3];
        }
    }
    float* ssred = (float*)(sm + 33792);
    __half* st2 = (__half*)(sm + A_ST2);
    __syncthreads();

    // softmax over k per column; quantize scores to fp16
    if (tid < 128) {
        int col = tid;
        float m = -1e30f;
#pragma unroll
        for (int k = 0; k < 64; k++) m = fmaxf(m, st[k * 132 + col]);
        float s = 0.f;
#pragma unroll
        for (int k = 0; k < 64; k++) {
            float e = __expf(st[k * 132 + col] - m);
            st[k * 132 + col] = e;
            s += e;
        }
        float inv = 1.f / s;
#pragma unroll
        for (int k = 0; k < 64; k++)
            st2[k * 128 + col] = __float2half_rn(st[k * 132 + col] * inv);
    }
    __syncthreads();

    // coalesced fp16 score writes + piggybacked per-row ssum (from quantized values)
#pragma unroll
    for (int r = 0; r < 8; r++) {
        int row = wid * 8 + r;
        uint2 v = ((const uint2*)&st2[row * 128])[lane];
        ((uint2*)&g_Sf[((size_t)b * K_ + row) * N_ + n0])[lane] = v;
        __half2 h0 = *(__half2*)&v.x, h1 = *(__half2*)&v.y;
        float2 f0 = __half22float2(h0), f1 = __half22float2(h1);
        float ws = (f0.x + f0.y) + (f1.x + f1.y);
#pragma unroll
        for (int o = 16; o > 0; o >>= 1) ws += __shfl_xor_sync(0xffffffff, ws, o);
        if (lane == 0) ssred[row] = ws;
    }
    __syncthreads();
    if (tid < 64) atomicAdd(&g_ssum[b * K_ + tid], ssred[tid]);
}

// ---------------------------------------------------------------------------
// Kernel B: agg_part[sp][128 d][64 k] = x @ s^T (reduce 512 n), fp16 2-pass:
// acc += x_hi*s + x_lo*s. Scores via cp.async, x split in-regs. Split-K 4.
#define PB 40
#define B_BUF  25600
#define B_SMEM (2 * B_BUF)

__global__ __launch_bounds__(256) void kB(const float* __restrict__ x) {
    extern __shared__ char sm[];
    const int b = blockIdx.y;
    const int d0 = (blockIdx.x & 3) * 128;
    const int sp = blockIdx.x >> 2;
    const int spn = sp * 512;
    const int tid = threadIdx.x, lane = tid & 31, wid = tid >> 5;
    const uint32_t smb = smem_u32(sm);

    const int xrr = tid >> 3, xnn = (tid & 7) * 4;   // x: d row base, n offset
    const int sr = tid >> 2, sq = (tid & 3) * 16;    // S cp.async: row, 16B quarter
    const size_t gs_base = ((size_t)b * K_ + sr) * N_ + spn;

    float acc[8][4];
#pragma unroll
    for (int i = 0; i < 8; i++)
#pragma unroll
        for (int j = 0; j < 4; j++) acc[i][j] = 0.f;

    {
        uint32_t dst = smb + 20480 + sr * 80 + sq;
        CP16(dst, (const char*)&g_Sf[gs_base] + sq);
        CP_COMMIT();
    }
    float4 xbuf[4];
#pragma unroll
    for (int p = 0; p < 4; p++)
        xbuf[p] = *(const float4*)&x[((size_t)b * D_ + d0 + xrr + p * 32) * N_ + spn + xnn];

    for (int c = 0; c < 16; c++) {
        char* bufc = sm + (c & 1) * B_BUF;
        __half* Xh = (__half*)(bufc);
        __half* Xl = (__half*)(bufc + 10240);

#pragma unroll
        for (int p = 0; p < 4; p++) {
            int rr = xrr + p * 32;
            uint32_t h0, l0, h1, l1;
            split2h(xbuf[p].x, xbuf[p].y, h0, l0);
            split2h(xbuf[p].z, xbuf[p].w, h1, l1);
            int off = rr * PB + xnn;
            *(uint32_t*)&Xh[off] = h0; *(uint32_t*)&Xh[off + 2] = h1;
            *(uint32_t*)&Xl[off] = l0; *(uint32_t*)&Xl[off + 2] = l1;
        }
        CP_WAIT0();
        __syncthreads();

        if (c < 15) {
            int n1 = (c + 1) * 32;
            uint32_t dst = smb + ((c + 1) & 1) * B_BUF + 20480 + sr * 80 + sq;
            CP16(dst, (const char*)&g_Sf[gs_base + n1] + sq);
            CP_COMMIT();
#pragma unroll
            for (int p = 0; p < 4; p++)
                xbuf[p] = *(const float4*)&x[((size_t)b * D_ + d0 + xrr + p * 32) * N_ + spn + n1 + xnn];
        }

        const uint32_t xh_a = smb + (c & 1) * B_BUF;
        const uint32_t xl_a = xh_a + 10240;
        const uint32_t s_a  = xh_a + 20480;
#pragma unroll
        for (int ks = 0; ks < 2; ks++) {
            uint32_t ah[4], al[4];
            uint32_t aoff = (uint32_t)(((wid * 16 + (lane & 15)) * PB + ks * 16 + (lane >> 4) * 8) * 2);
            ldsm4(ah, xh_a + aoff);
            ldsm4(al, xl_a + aoff);
#pragma unroll
            for (int nf = 0; nf < 4; nf++) {
                uint32_t bh[4];
                uint32_t boff = (uint32_t)(((nf * 16 + (lane & 7) + ((lane >> 4) << 3)) * PB +
                                            ks * 16 + ((lane >> 3) & 1) * 8) * 2);
                ldsm4(bh, s_a + boff);
                mma_f16(acc[nf * 2],     ah, bh);
                mma_f16(acc[nf * 2],     al, bh);
                mma_f16(acc[nf * 2 + 1], ah, bh + 2);
                mma_f16(acc[nf * 2 + 1], al, bh + 2);
            }
        }
    }

    int g = lane >> 2, tg = lane & 3;
    int d = d0 + wid * 16 + g;
    float* base = &g_aggp[sp][((size_t)b * D_ + d) * K_];
#pragma unroll
    for (int nf = 0; nf < 8; nf++) {
        int cix = nf * 8 + tg * 2;
        base[cix]              = acc[nf][0];
        base[cix + 1]          = acc[nf][1];
        base[8 * K_ + cix]     = acc[nf][2];
        base[8 * K_ + cix + 1] = acc[nf][3];
    }
}

// ---------------------------------------------------------------------------
// Fused epilogue: one block per batch. v = sum(parts) - centers*ssum held in
// smem; intranorm sumsq -> mult -> final writes. Replaces 3 kernels.
#define EP_V    0
#define EP_CS   (D_ * K_ * 4)
#define EP_SMEM (EP_CS + 256 + 256)

__global__ __launch_bounds__(1024) void k_epi(const float* __restrict__ centers,
                                              float* __restrict__ out) {
    extern __shared__ char sm[];
    float* v     = (float*)sm;                 // [32768]
    float* colss = (float*)(sm + EP_CS);       // [64]
    float* aft   = (float*)(sm + EP_CS + 256); // [64]
    const int b = blockIdx.x;
    const int t = threadIdx.x;
    const int k = t & 63;

    if (t < 64) colss[t] = 0.f;
    __syncthreads();

    const float ssumk = g_ssum[b * K_ + k];
    const size_t base = (size_t)b * D_ * K_;
    float accs = 0.f;
#pragma unroll
    for (int i = 0; i < 32; i++) {
        int idx = t + i * 1024;   // idx % 64 == k
        float val = g_aggp[0][base + idx] + g_aggp[1][base + idx]
                  + g_aggp[2][base + idx] + g_aggp[3][base + idx]
                  - centers[idx] * ssumk;
        v[idx] = val;
        accs = fmaf(val, val, accs);
    }
    atomicAdd(&colss[k], accs);
    __syncthreads();

    if (t < 64) {
        float ss = colss[t];
        float m = fmaxf(sqrtf(ss), 1e-12f);
        aft[t] = ss / (m * m);
        colss[t] = 1.f / m;
    }
    __syncthreads();
    if (t < 32) {
        float s = aft[t] + aft[t + 32];
#pragma unroll
        for (int o = 16; o > 0; o >>= 1) s += __shfl_xor_sync(0xffffffff, s, o);
        if (t == 0) aft[0] = 1.f / fmaxf(sqrtf(s), 1e-12f);
    }
    __syncthreads();

    const float multk = aft[0] * colss[k];
    float* op = &out[base];
#pragma unroll
    for (int i = 0; i < 32; i++) {
        int idx = t + i * 1024;
        op[idx] = v[idx] * multk;
    }
}

// ---------------------------------------------------------------------------
extern "C" void kernel_launch(void* const* d_in, const int* in_sizes, int n_in,
                              void* d_out, int out_size) {
    const float* x       = (const float*)d_in[0];  // [B, D, N]
    const float* W       = (const float*)d_in[1];  // [K, D]
    const float* centers = (const float*)d_in[2];  // [D, K]
    float* out = (float*)d_out;                    // [B, D*K]

    cudaFuncSetAttribute(kA,    cudaFuncAttributeMaxDynamicSharedMemorySize, A_SMEM);
    cudaFuncSetAttribute(kB,    cudaFuncAttributeMaxDynamicSharedMemorySize, B_SMEM);
    cudaFuncSetAttribute(k_epi, cudaFuncAttributeMaxDynamicSharedMemorySize, EP_SMEM);

    k_prep<<<32, 256>>>(W);
    dim3 gA(N_ / 128, B_);
    kA<<<gA, 256, A_SMEM>>>(x);
    dim3 gB(16, B_);           // 4 d-tiles x 4 n-splits
    kB<<<gB, 256, B_SMEM>>>(x);
    k_epi<<<B_, 1024, EP_SMEM>>>(centers, out);
}